// round 8
// baseline (speedup 1.0000x reference)
#include <cuda_runtime.h>
#include <cuda_bf16.h>
#include <cstdint>
#include <cstring>

#define Nn 1024
#define Mm 256
#define Bb 1024
#define Kk 1280
#define TMt 128           // CTA tile rows
#define TNt 64            // CTA tile cols
#define TKt 32            // K per staged tile
#define NTIL 40
#define BETA 0.01f
#define EPSL 1e-12f
#define THREADS 256

typedef uint32_t u32;

// smem plane layout (same as R7): bf16 rows padded to 80B -> conflict-free frag LDS
#define APL (128 * 80)
#define BPL (64 * 80)
#define BUFSZ (6 * APL + 6 * BPL)    // Arh,Arl,Aih,Ail,Ash,Asl | Brh,Brl,Bih,Bil,Bsh,Bsl
#define SMTOT (2 * BUFSZ)            // 184320 B

// Precomputed bf16 planes. A = [Toeplitz(v) | W2], row-major [n][k] 1024x1280.
// BT = [x;y]^T, [b][k] 1024x1280. Plane order: rh,rl,ih,il,sh,sl (s = re+im).
__device__ __nv_bfloat16 gA[6][1024 * 1280];
__device__ __nv_bfloat16 gBT[6][1024 * 1280];

static __device__ __forceinline__ void split6(float ar, float ai,
    __nv_bfloat16& rh, __nv_bfloat16& rl, __nv_bfloat16& ih, __nv_bfloat16& il,
    __nv_bfloat16& sh, __nv_bfloat16& sl) {
    rh = __float2bfloat16_rn(ar); rl = __float2bfloat16_rn(ar - __bfloat162float(rh));
    ih = __float2bfloat16_rn(ai); il = __float2bfloat16_rn(ai - __bfloat162float(ih));
    float s = ar + ai;
    sh = __float2bfloat16_rn(s);  sl = __float2bfloat16_rn(s - __bfloat162float(sh));
}

// ---- prep A: expand Toeplitz + W2 into 6 bf16 planes ----
__global__ void prep_a_kernel(const float* __restrict__ v_re, const float* __restrict__ v_im,
                              const float* __restrict__ W2_re, const float* __restrict__ W2_im) {
    const int n = blockIdx.y;
    const int k = blockIdx.x * blockDim.x + threadIdx.x;   // 0..1279
    float ar, ai;
    if (k < Nn) { int g = 1023 + n - k; ar = v_re[g]; ai = v_im[g]; }
    else        { int g = n * Mm + (k - Nn); ar = W2_re[g]; ai = W2_im[g]; }
    __nv_bfloat16 rh, rl, ih, il, sh, sl;
    split6(ar, ai, rh, rl, ih, il, sh, sl);
    const int o = n * Kk + k;
    gA[0][o] = rh; gA[1][o] = rl; gA[2][o] = ih; gA[3][o] = il; gA[4][o] = sh; gA[5][o] = sl;
}

// ---- prep B: transpose [x;y] (k-major) into [b][k] bf16 planes ----
__global__ void prep_b_kernel(const float* __restrict__ x_re, const float* __restrict__ x_im,
                              const float* __restrict__ y_re, const float* __restrict__ y_im) {
    __shared__ __nv_bfloat16 t[6][32][33];
    const int tid = threadIdx.x;
    const int k0 = blockIdx.x * 32;
    const int b0 = blockIdx.y * 32;
    const int jj = tid & 31, i0 = tid >> 5;
    #pragma unroll
    for (int it = 0; it < 4; ++it) {
        int i = i0 + it * 8;
        int k = k0 + i, b = b0 + jj;
        float ar = (k < Nn) ? x_re[k * Bb + b] : y_re[(k - Nn) * Bb + b];
        float ai = (k < Nn) ? x_im[k * Bb + b] : y_im[(k - Nn) * Bb + b];
        __nv_bfloat16 rh, rl, ih, il, sh, sl;
        split6(ar, ai, rh, rl, ih, il, sh, sl);
        t[0][jj][i] = rh; t[1][jj][i] = rl; t[2][jj][i] = ih;
        t[3][jj][i] = il; t[4][jj][i] = sh; t[5][jj][i] = sl;
    }
    __syncthreads();
    #pragma unroll
    for (int it = 0; it < 4; ++it) {
        int j = i0 + it * 8;
        int i = jj;
        int o = (b0 + j) * Kk + k0 + i;
        #pragma unroll
        for (int p = 0; p < 6; ++p) gBT[p][o] = t[p][j][i];
    }
}

static __device__ __forceinline__ u32 smem_u32(const void* p) {
    u32 a;
    asm("{ .reg .u64 t; cvta.to.shared.u64 t, %1; cvt.u32.u64 %0, t; }" : "=r"(a) : "l"(p));
    return a;
}
static __device__ __forceinline__ void cp16(u32 dst, const void* src) {
    asm volatile("cp.async.cg.shared.global [%0], [%1], 16;" :: "r"(dst), "l"(src));
}
static __device__ __forceinline__ void mma16816(float* c, const u32* a, const u32* b) {
    asm volatile(
        "mma.sync.aligned.m16n8k16.row.col.f32.bf16.bf16.f32 "
        "{%0,%1,%2,%3}, {%4,%5,%6,%7}, {%8,%9}, {%0,%1,%2,%3};"
        : "+f"(c[0]), "+f"(c[1]), "+f"(c[2]), "+f"(c[3])
        : "r"(a[0]), "r"(a[1]), "r"(a[2]), "r"(a[3]), "r"(b[0]), "r"(b[1]));
}

// z = softthresh(W1 @ x + W2 @ y); split-2 bf16 + Gauss on mma.sync, cp.async staged.
__global__ __launch_bounds__(THREADS, 1)
void toeplitz_hmma2_kernel(void* __restrict__ out, int omode)
{
    extern __shared__ char smem[];
    const int tid = threadIdx.x;
    const int wid = tid >> 5;
    const int lid = tid & 31;
    const int wr = wid >> 1, wc = wid & 1;     // 4x2 warp grid
    const int wm = wr * 32, wn = wc * 32;      // warp tile 32x32
    const int r4 = lid >> 2;
    const int c2 = (lid & 3) * 2;
    const int row0 = blockIdx.y * TMt;
    const int col0 = blockIdx.x * TNt;

    float acc[3][2][4][4];
    #pragma unroll
    for (int p = 0; p < 3; ++p)
        #pragma unroll
        for (int mt = 0; mt < 2; ++mt)
            #pragma unroll
            for (int nt = 0; nt < 4; ++nt)
                #pragma unroll
                for (int q = 0; q < 4; ++q) acc[p][mt][nt][q] = 0.0f;

    auto issue = [&](int t, int bf) {
        char* base = smem + bf * BUFSZ;
        const int k0 = t * TKt;
        #pragma unroll
        for (int i = 0; i < 12; ++i) {                 // A: 6 planes x 128 rows x 4 chunks
            int c = tid + i * THREADS;                 // 0..3071
            int p = c >> 9, r = c & 511;
            int n = r >> 2, q = r & 3;
            cp16(smem_u32(base + p * APL + n * 80 + q * 16),
                 &gA[p][(row0 + n) * Kk + k0 + q * 8]);
        }
        #pragma unroll
        for (int i = 0; i < 6; ++i) {                  // B: 6 planes x 64 cols x 4 chunks
            int c = tid + i * THREADS;                 // 0..1535
            int p = c >> 8, r = c & 255;
            int cc = r >> 2, q = r & 3;
            cp16(smem_u32(base + 6 * APL + p * BPL + cc * 80 + q * 16),
                 &gBT[p][(col0 + cc) * Kk + k0 + q * 8]);
        }
        asm volatile("cp.async.commit_group;" ::: "memory");
    };

    issue(0, 0);

    for (int t = 0; t < NTIL; ++t) {
        const int buf = t & 1;
        if (t + 1 < NTIL) {
            issue(t + 1, buf ^ 1);
            asm volatile("cp.async.wait_group 1;" ::: "memory");
        } else {
            asm volatile("cp.async.wait_group 0;" ::: "memory");
        }
        __syncthreads();

        char* base = smem + buf * BUFSZ;
        #pragma unroll
        for (int ks = 0; ks < 2; ++ks) {
            const u32 kbB = (u32)(ks * 32);
            #pragma unroll
            for (int p = 0; p < 3; ++p) {
                char* Ah = base + (2 * p) * APL;
                char* Al = Ah + APL;
                char* Bh = base + 6 * APL + (2 * p) * BPL;
                char* Bl = Bh + BPL;
                u32 ah[2][4], al[2][4], bh[4][2], bl[4][2];
                #pragma unroll
                for (int mt = 0; mt < 2; ++mt) {
                    u32 o = (u32)((wm + mt * 16 + r4) * 80) + kbB + (u32)(c2 * 2);
                    ah[mt][0] = *(u32*)(Ah + o);
                    ah[mt][1] = *(u32*)(Ah + o + 8 * 80);
                    ah[mt][2] = *(u32*)(Ah + o + 16);
                    ah[mt][3] = *(u32*)(Ah + o + 8 * 80 + 16);
                    al[mt][0] = *(u32*)(Al + o);
                    al[mt][1] = *(u32*)(Al + o + 8 * 80);
                    al[mt][2] = *(u32*)(Al + o + 16);
                    al[mt][3] = *(u32*)(Al + o + 8 * 80 + 16);
                }
                #pragma unroll
                for (int nt = 0; nt < 4; ++nt) {
                    u32 o = (u32)((wn + nt * 8 + r4) * 80) + kbB + (u32)(c2 * 2);
                    bh[nt][0] = *(u32*)(Bh + o);
                    bh[nt][1] = *(u32*)(Bh + o + 16);
                    bl[nt][0] = *(u32*)(Bl + o);
                    bl[nt][1] = *(u32*)(Bl + o + 16);
                }
                #pragma unroll
                for (int mt = 0; mt < 2; ++mt)
                    #pragma unroll
                    for (int nt = 0; nt < 4; ++nt) {
                        mma16816(acc[p][mt][nt], ah[mt], bh[nt]);
                        mma16816(acc[p][mt][nt], ah[mt], bl[nt]);
                        mma16816(acc[p][mt][nt], al[mt], bh[nt]);
                    }
            }
        }
        __syncthreads();
    }

    // ---- epilogue: re = P1-P2, im = P3-P1-P2, soft-threshold, store ----
    #pragma unroll
    for (int mt = 0; mt < 2; ++mt) {
        #pragma unroll
        for (int nt = 0; nt < 4; ++nt) {
            #pragma unroll
            for (int half = 0; half < 2; ++half) {
                const int q0 = half * 2;
                const int row = row0 + wm + mt * 16 + r4 + half * 8;
                const int col = col0 + wn + nt * 8 + c2;
                float p1a = acc[0][mt][nt][q0],     p1b = acc[0][mt][nt][q0 + 1];
                float p2a = acc[1][mt][nt][q0],     p2b = acc[1][mt][nt][q0 + 1];
                float p3a = acc[2][mt][nt][q0],     p3b = acc[2][mt][nt][q0 + 1];
                float rea = p1a - p2a,  reb = p1b - p2b;
                float ima = p3a - p1a - p2a, imb = p3b - p1b - p2b;
                float maga = sqrtf(rea * rea + ima * ima);
                float sca  = fmaxf(maga - BETA, 0.0f) / fmaxf(maga, EPSL);
                float magb = sqrtf(reb * reb + imb * imb);
                float scb  = fmaxf(magb - BETA, 0.0f) / fmaxf(magb, EPSL);
                rea *= sca; ima *= sca; reb *= scb; imb *= scb;
                const int e = row * Bb + col;
                if (omode == 0) {
                    __nv_bfloat162 pa = __floats2bfloat162_rn(rea, ima);
                    __nv_bfloat162 pb = __floats2bfloat162_rn(reb, imb);
                    u32 ua, ub; memcpy(&ua, &pa, 4); memcpy(&ub, &pb, 4);
                    *(uint2*)((u32*)out + e) = make_uint2(ua, ub);
                } else {
                    *(float2*)((float*)out + e) = make_float2(rea, reb);
                }
            }
        }
    }
}

extern "C" void kernel_launch(void* const* d_in, const int* in_sizes, int n_in,
                              void* d_out, int out_size) {
    // Crash-proof input dispatch: classify by element count (elements or bytes).
    int scale = 1;
    bool have2047 = false, have8188 = false;
    for (int i = 0; i < n_in && i < 8; ++i) {
        if (in_sizes[i] == 2 * Nn - 1) have2047 = true;
        if (in_sizes[i] == (2 * Nn - 1) * 4) have8188 = true;
    }
    if (!have2047 && have8188) scale = 4;

    const float* vp[2] = {0, 0};
    const float* xp[2] = {0, 0};
    const float* mp[4] = {0, 0, 0, 0};
    int nv = 0, nx = 0, nm = 0;
    for (int i = 0; i < n_in && i < 8; ++i) {
        const float* p = (const float*)d_in[i];
        long s = in_sizes[i];
        if (s == (long)(2 * Nn - 1) * scale)      { if (nv < 2) vp[nv++] = p; }
        else if (s == (long)Nn * Bb * scale)      { if (nx < 2) xp[nx++] = p; }
        else if (s == (long)Nn * Mm * scale)      { if (nm < 4) mp[nm++] = p; }
    }
    const float* v_re  = vp[0] ? vp[0] : (const float*)d_in[0];
    const float* v_im  = vp[1] ? vp[1] : (const float*)d_in[1];
    const float* W2_re = mp[0] ? mp[0] : (const float*)d_in[2];
    const float* W2_im = mp[1] ? mp[1] : (const float*)d_in[3];
    const float* x_re  = xp[0] ? xp[0] : (const float*)d_in[4];
    const float* x_im  = xp[1] ? xp[1] : (const float*)d_in[5];
    const float* y_re  = mp[2] ? mp[2] : (const float*)d_in[6];
    const float* y_im  = mp[3] ? mp[3] : (const float*)d_in[7];

    const int omode = (out_size >= 2 * Nn * Bb) ? 0 : 1;

    // prep: expand + convert once (removes 8-16x redundant per-CTA conversion)
    prep_a_kernel<<<dim3(Kk / 256, Nn), 256>>>(v_re, v_im, W2_re, W2_im);
    prep_b_kernel<<<dim3(Kk / 32, Bb / 32), 256>>>(x_re, x_im, y_re, y_im);

    cudaFuncSetAttribute(toeplitz_hmma2_kernel,
                         cudaFuncAttributeMaxDynamicSharedMemorySize, SMTOT);
    dim3 grid(Bb / TNt, Nn / TMt);   // (16, 8) = 128 CTAs
    toeplitz_hmma2_kernel<<<grid, THREADS, SMTOT>>>(d_out, omode);
}

// round 9
// speedup vs baseline: 1.0725x; 1.0725x over previous
#include <cuda_runtime.h>
#include <cuda_bf16.h>
#include <cstdint>
#include <cstring>

#define Nn 1024
#define Mm 256
#define Bb 1024
#define Kk 1280
#define TMt 128           // CTA tile rows
#define TNt 64            // CTA tile cols
#define TKt 32            // K per staged tile
#define NTIL 40
#define BETA 0.01f
#define EPSL 1e-12f
#define THREADS 512

typedef uint32_t u32;

// smem plane layout: bf16 rows padded to 80B -> conflict-free ldmatrix phases
#define APL (128 * 80)
#define BPL (64 * 80)
#define BUFSZ (6 * APL + 6 * BPL)    // Arh,Arl,Aih,Ail,Ash,Asl | Brh,Brl,Bih,Bil,Bsh,Bsl
#define SMTOT (2 * BUFSZ)            // 184320 B

static __device__ __forceinline__ void hilo(float a, float b, u32& h, u32& l) {
    __nv_bfloat162 t = __floats2bfloat162_rn(a, b);
    u32 hu; memcpy(&hu, &t, 4);
    h = hu;
    float fa = __uint_as_float(hu << 16);
    float fb = __uint_as_float(hu & 0xFFFF0000u);
    __nv_bfloat162 t2 = __floats2bfloat162_rn(a - fa, b - fb);
    memcpy(&l, &t2, 4);
}
static __device__ __forceinline__ u32 smem_u32(const void* p) {
    u32 a;
    asm("{ .reg .u64 t; cvta.to.shared.u64 t, %1; cvt.u32.u64 %0, t; }" : "=r"(a) : "l"(p));
    return a;
}
static __device__ __forceinline__ void ldsm4(u32 addr, u32& r0, u32& r1, u32& r2, u32& r3) {
    asm volatile("ldmatrix.sync.aligned.m8n8.x4.shared.b16 {%0,%1,%2,%3}, [%4];"
                 : "=r"(r0), "=r"(r1), "=r"(r2), "=r"(r3) : "r"(addr));
}
static __device__ __forceinline__ void mma16816(float* c, const u32* a, u32 b0, u32 b1) {
    asm volatile(
        "mma.sync.aligned.m16n8k16.row.col.f32.bf16.bf16.f32 "
        "{%0,%1,%2,%3}, {%4,%5,%6,%7}, {%8,%9}, {%0,%1,%2,%3};"
        : "+f"(c[0]), "+f"(c[1]), "+f"(c[2]), "+f"(c[3])
        : "r"(a[0]), "r"(a[1]), "r"(a[2]), "r"(a[3]), "r"(b0), "r"(b1));
}

// z = softthresh(W1 @ x + W2 @ y); W1[n,k]=v[N-1+n-k].
// Split-2 bf16 + Gauss 3-product on mma.sync; ldmatrix fragments; 16 warps.
__global__ __launch_bounds__(THREADS, 1)
void toeplitz_hmma3_kernel(
    const float* __restrict__ v_re,  const float* __restrict__ v_im,
    const float* __restrict__ W2_re, const float* __restrict__ W2_im,
    const float* __restrict__ x_re,  const float* __restrict__ x_im,
    const float* __restrict__ y_re,  const float* __restrict__ y_im,
    void* __restrict__ out, int omode)
{
    extern __shared__ char smem[];
    const u32 smb = smem_u32(smem);
    const int tid = threadIdx.x;
    const int wid = tid >> 5;
    const int lid = tid & 31;
    const int wm = (wid >> 1) * 16;           // 8x2 warp grid, warp tile 16x32
    const int wn = (wid & 1) * 32;
    const int r4 = lid >> 2;
    const int c2 = (lid & 3) * 2;
    const int row0 = blockIdx.y * TMt;
    const int col0 = blockIdx.x * TNt;

    // ldmatrix per-lane offsets (within a plane)
    const int l8 = (lid & 7) + ((lid >> 3) & 1) * 8;
    const u32 aoff = (u32)((wm + l8) * 80 + (lid >> 4) * 16);
    const u32 boff0 = (u32)((wn + l8) * 80 + (lid >> 4) * 16);        // n tiles 0,1
    const u32 boff1 = (u32)((wn + 16 + l8) * 80 + (lid >> 4) * 16);   // n tiles 2,3

    float acc[3][4][4];   // [plane P1/P2/P3][nt][quad]
    #pragma unroll
    for (int p = 0; p < 3; ++p)
        #pragma unroll
        for (int nt = 0; nt < 4; ++nt)
            #pragma unroll
            for (int q = 0; q < 4; ++q) acc[p][nt][q] = 0.0f;

    // staging regs (fused fp32->bf16 hi/lo conversion, R7-proven)
    float Ar0[4], Ar1[4], Ai0[4], Ai1[4];
    float Br0[2], Br1[2], Bi0[2], Bi1[2];

    auto load_regs = [&](int t) {
        const int k0 = t * TKt;
        if (k0 < Nn) {
            #pragma unroll
            for (int it = 0; it < 4; ++it) {
                int idx = tid + it * THREADS;      // 0..2047
                int kp = idx & 15, n = idx >> 4;   // k = 2*kp
                int g = 1023 + (row0 + n) - (k0 + 2 * kp);
                Ar0[it] = v_re[g]; Ar1[it] = v_re[g - 1];
                Ai0[it] = v_im[g]; Ai1[it] = v_im[g - 1];
            }
        } else {
            #pragma unroll
            for (int it = 0; it < 4; ++it) {
                int idx = tid + it * THREADS;
                int kp = idx & 15, n = idx >> 4;
                int g = (row0 + n) * Mm + (k0 - Nn + 2 * kp);
                Ar0[it] = W2_re[g]; Ar1[it] = W2_re[g + 1];
                Ai0[it] = W2_im[g]; Ai1[it] = W2_im[g + 1];
            }
        }
        const float* sr = (k0 < Nn) ? x_re : y_re;
        const float* si = (k0 < Nn) ? x_im : y_im;
        const int kb = (k0 < Nn) ? k0 : (k0 - Nn);
        #pragma unroll
        for (int it = 0; it < 2; ++it) {
            int idx = tid + it * THREADS;          // 0..1023
            int cc = idx & 63, kp = idx >> 6;      // k = 2*kp
            int g = (kb + 2 * kp) * Bb + col0 + cc;
            Br0[it] = sr[g]; Br1[it] = sr[g + Bb];
            Bi0[it] = si[g]; Bi1[it] = si[g + Bb];
        }
    };

    auto store_smem = [&](int bf) {
        char* base = smem + bf * BUFSZ;
        #pragma unroll
        for (int it = 0; it < 4; ++it) {
            int idx = tid + it * THREADS;
            int kp = idx & 15, n = idx >> 4;
            u32 off = (u32)(n * 80 + kp * 4);
            u32 h, l;
            hilo(Ar0[it], Ar1[it], h, l);
            *(u32*)(base + off) = h; *(u32*)(base + APL + off) = l;
            hilo(Ai0[it], Ai1[it], h, l);
            *(u32*)(base + 2 * APL + off) = h; *(u32*)(base + 3 * APL + off) = l;
            hilo(Ar0[it] + Ai0[it], Ar1[it] + Ai1[it], h, l);
            *(u32*)(base + 4 * APL + off) = h; *(u32*)(base + 5 * APL + off) = l;
        }
        char* Bb0 = base + 6 * APL;
        #pragma unroll
        for (int it = 0; it < 2; ++it) {
            int idx = tid + it * THREADS;
            int cc = idx & 63, kp = idx >> 6;
            u32 off = (u32)(cc * 80 + kp * 4);
            u32 h, l;
            hilo(Br0[it], Br1[it], h, l);
            *(u32*)(Bb0 + off) = h; *(u32*)(Bb0 + BPL + off) = l;
            hilo(Bi0[it], Bi1[it], h, l);
            *(u32*)(Bb0 + 2 * BPL + off) = h; *(u32*)(Bb0 + 3 * BPL + off) = l;
            hilo(Br0[it] + Bi0[it], Br1[it] + Bi1[it], h, l);
            *(u32*)(Bb0 + 4 * BPL + off) = h; *(u32*)(Bb0 + 5 * BPL + off) = l;
        }
    };

    load_regs(0);
    store_smem(0);
    __syncthreads();

    for (int t = 0; t < NTIL; ++t) {
        const int buf = t & 1;
        if (t + 1 < NTIL) load_regs(t + 1);

        const u32 base = smb + buf * BUFSZ;
        #pragma unroll
        for (int ks = 0; ks < 2; ++ks) {
            const u32 kb = (u32)(ks * 32);
            #pragma unroll
            for (int p = 0; p < 3; ++p) {
                const u32 Ah = base + (2 * p) * APL;
                const u32 Al = Ah + APL;
                const u32 Bh = base + 6 * APL + (2 * p) * BPL;
                const u32 Bl = Bh + BPL;
                u32 ah[4], al[4];
                u32 bh[4], bl[4];   // [ntpair*2 + b-half]
                ldsm4(Ah + aoff + kb, ah[0], ah[1], ah[2], ah[3]);
                ldsm4(Al + aoff + kb, al[0], al[1], al[2], al[3]);
                ldsm4(Bh + boff0 + kb, bh[0], bh[1], bh[2], bh[3]);
                ldsm4(Bl + boff0 + kb, bl[0], bl[1], bl[2], bl[3]);
                #pragma unroll
                for (int nt = 0; nt < 2; ++nt) {
                    mma16816(acc[p][nt], ah, bh[nt], bh[nt + 2]);
                    mma16816(acc[p][nt], ah, bl[nt], bl[nt + 2]);
                    mma16816(acc[p][nt], al, bh[nt], bh[nt + 2]);
                }
                ldsm4(Bh + boff1 + kb, bh[0], bh[1], bh[2], bh[3]);
                ldsm4(Bl + boff1 + kb, bl[0], bl[1], bl[2], bl[3]);
                #pragma unroll
                for (int nt = 0; nt < 2; ++nt) {
                    mma16816(acc[p][nt + 2], ah, bh[nt], bh[nt + 2]);
                    mma16816(acc[p][nt + 2], ah, bl[nt], bl[nt + 2]);
                    mma16816(acc[p][nt + 2], al, bh[nt], bh[nt + 2]);
                }
            }
        }

        if (t + 1 < NTIL) store_smem(buf ^ 1);
        __syncthreads();
    }

    // ---- epilogue: re = P1-P2, im = P3-P1-P2, soft-threshold, store ----
    #pragma unroll
    for (int nt = 0; nt < 4; ++nt) {
        #pragma unroll
        for (int half = 0; half < 2; ++half) {
            const int q0 = half * 2;
            const int row = row0 + wm + r4 + half * 8;
            const int col = col0 + wn + nt * 8 + c2;
            float p1a = acc[0][nt][q0],     p1b = acc[0][nt][q0 + 1];
            float p2a = acc[1][nt][q0],     p2b = acc[1][nt][q0 + 1];
            float p3a = acc[2][nt][q0],     p3b = acc[2][nt][q0 + 1];
            float rea = p1a - p2a,  reb = p1b - p2b;
            float ima = p3a - p1a - p2a, imb = p3b - p1b - p2b;
            float maga = sqrtf(rea * rea + ima * ima);
            float sca  = fmaxf(maga - BETA, 0.0f) / fmaxf(maga, EPSL);
            float magb = sqrtf(reb * reb + imb * imb);
            float scb  = fmaxf(magb - BETA, 0.0f) / fmaxf(magb, EPSL);
            rea *= sca; ima *= sca; reb *= scb; imb *= scb;
            const int e = row * Bb + col;
            if (omode == 0) {
                __nv_bfloat162 pa = __floats2bfloat162_rn(rea, ima);
                __nv_bfloat162 pb = __floats2bfloat162_rn(reb, imb);
                u32 ua, ub; memcpy(&ua, &pa, 4); memcpy(&ub, &pb, 4);
                *(uint2*)((u32*)out + e) = make_uint2(ua, ub);
            } else {
                *(float2*)((float*)out + e) = make_float2(rea, reb);
            }
        }
    }
}

extern "C" void kernel_launch(void* const* d_in, const int* in_sizes, int n_in,
                              void* d_out, int out_size) {
    // Crash-proof input dispatch: classify by element count (elements or bytes).
    int scale = 1;
    bool have2047 = false, have8188 = false;
    for (int i = 0; i < n_in && i < 8; ++i) {
        if (in_sizes[i] == 2 * Nn - 1) have2047 = true;
        if (in_sizes[i] == (2 * Nn - 1) * 4) have8188 = true;
    }
    if (!have2047 && have8188) scale = 4;

    const float* vp[2] = {0, 0};
    const float* xp[2] = {0, 0};
    const float* mp[4] = {0, 0, 0, 0};
    int nv = 0, nx = 0, nm = 0;
    for (int i = 0; i < n_in && i < 8; ++i) {
        const float* p = (const float*)d_in[i];
        long s = in_sizes[i];
        if (s == (long)(2 * Nn - 1) * scale)      { if (nv < 2) vp[nv++] = p; }
        else if (s == (long)Nn * Bb * scale)      { if (nx < 2) xp[nx++] = p; }
        else if (s == (long)Nn * Mm * scale)      { if (nm < 4) mp[nm++] = p; }
    }
    const float* v_re  = vp[0] ? vp[0] : (const float*)d_in[0];
    const float* v_im  = vp[1] ? vp[1] : (const float*)d_in[1];
    const float* W2_re = mp[0] ? mp[0] : (const float*)d_in[2];
    const float* W2_im = mp[1] ? mp[1] : (const float*)d_in[3];
    const float* x_re  = xp[0] ? xp[0] : (const float*)d_in[4];
    const float* x_im  = xp[1] ? xp[1] : (const float*)d_in[5];
    const float* y_re  = mp[2] ? mp[2] : (const float*)d_in[6];
    const float* y_im  = mp[3] ? mp[3] : (const float*)d_in[7];

    const int omode = (out_size >= 2 * Nn * Bb) ? 0 : 1;

    cudaFuncSetAttribute(toeplitz_hmma3_kernel,
                         cudaFuncAttributeMaxDynamicSharedMemorySize, SMTOT);
    dim3 grid(Bb / TNt, Nn / TMt);   // (16, 8) = 128 CTAs
    toeplitz_hmma3_kernel<<<grid, THREADS, SMTOT>>>(
        v_re, v_im, W2_re, W2_im, x_re, x_im, y_re, y_im,
        d_out, omode);
}

// round 10
// speedup vs baseline: 1.2289x; 1.1459x over previous
#include <cuda_runtime.h>
#include <cuda_bf16.h>
#include <cstdint>
#include <cstring>

#define Nn 1024
#define Mm 256
#define Bb 1024
#define Kk 1280
#define TMt 128           // CTA tile rows
#define TNt 64            // CTA tile cols
#define TKt 32            // K per staged tile
#define NTIL 40
#define BETA 0.01f
#define EPSL 1e-12f
#define THREADS 256

typedef uint32_t u32;

// Fragment-packed plane layout (per k-tile):
//  A plane: [m16 tile 0..7][kstep 0..1][lane 0..31][16B]  = 8192 B
//  B plane: [n8-pair 0..3][kstep 0..1][lane 0..31][16B]   = 4096 B
// One LDS.128 per lane yields a complete mma fragment (a0..a3 / b0,b1 x 2 tiles).
#define APL 8192
#define BPL 4096
#define BUFSZ (6 * APL + 6 * BPL)    // Arh,Arl,Aih,Ail,Ash,Asl | Brh,..,Bsl = 73728
#define SMTOT (2 * BUFSZ)            // 147456 B

static __device__ __forceinline__ void hilo(float a, float b, u32& h, u32& l) {
    __nv_bfloat162 t = __floats2bfloat162_rn(a, b);
    u32 hu; memcpy(&hu, &t, 4);
    h = hu;
    float fa = __uint_as_float(hu << 16);
    float fb = __uint_as_float(hu & 0xFFFF0000u);
    __nv_bfloat162 t2 = __floats2bfloat162_rn(a - fa, b - fb);
    memcpy(&l, &t2, 4);
}
static __device__ __forceinline__ u32 smem_u32(const void* p) {
    u32 a;
    asm("{ .reg .u64 t; cvta.to.shared.u64 t, %1; cvt.u32.u64 %0, t; }" : "=r"(a) : "l"(p));
    return a;
}
static __device__ __forceinline__ uint4 lds128(u32 addr) {
    uint4 r;
    asm volatile("ld.shared.v4.b32 {%0,%1,%2,%3}, [%4];"
                 : "=r"(r.x), "=r"(r.y), "=r"(r.z), "=r"(r.w) : "r"(addr));
    return r;
}
static __device__ __forceinline__ void mma16816(float* c, const uint4& a, u32 b0, u32 b1) {
    asm volatile(
        "mma.sync.aligned.m16n8k16.row.col.f32.bf16.bf16.f32 "
        "{%0,%1,%2,%3}, {%4,%5,%6,%7}, {%8,%9}, {%0,%1,%2,%3};"
        : "+f"(c[0]), "+f"(c[1]), "+f"(c[2]), "+f"(c[3])
        : "r"(a.x), "r"(a.y), "r"(a.z), "r"(a.w), "r"(b0), "r"(b1));
}

// STS offset for A value (n, kp): bf16x2 of k=2kp,2kp+1 at row n.
static __device__ __forceinline__ u32 sts_off_a(int n, int kp) {
    int kpp = kp & 7;
    return (u32)((n >> 4) * 1024 + (kp >> 3) * 512 +
                 (((n & 7) * 4 + (kpp & 3)) * 16) +
                 (((kpp >= 4) ? 2 : 0) + ((n >> 3) & 1)) * 4);
}
// STS offset for B value (c, kp): bf16x2 of k=2kp,2kp+1 at col c.
static __device__ __forceinline__ u32 sts_off_b(int c, int kp) {
    int kpp = kp & 7;
    return (u32)((c >> 4) * 1024 + (kp >> 3) * 512 +
                 (((c & 7) * 4 + (kpp & 3)) * 16) +
                 ((((c >> 3) & 1) * 2) + ((kpp >= 4) ? 1 : 0)) * 4);
}

// z = softthresh(W1 @ x + W2 @ y); W1[n,k]=v[N-1+n-k].
// Split-2 bf16 + Gauss 3-product on mma.sync; fragment-packed smem (LDS.128).
__global__ __launch_bounds__(THREADS, 1)
void toeplitz_hmma4_kernel(
    const float* __restrict__ v_re,  const float* __restrict__ v_im,
    const float* __restrict__ W2_re, const float* __restrict__ W2_im,
    const float* __restrict__ x_re,  const float* __restrict__ x_im,
    const float* __restrict__ y_re,  const float* __restrict__ y_im,
    void* __restrict__ out, int omode)
{
    extern __shared__ char smem[];
    const u32 smb = smem_u32(smem);
    const int tid = threadIdx.x;
    const int wid = tid >> 5;
    const int lid = tid & 31;
    const int wr = wid >> 1, wc = wid & 1;    // 4x2 warp grid, warp tile 32x32
    const int r4 = lid >> 2;
    const int c2 = (lid & 3) * 2;
    const int row0 = blockIdx.y * TMt;
    const int col0 = blockIdx.x * TNt;
    const u32 lane16 = (u32)(lid * 16);

    float acc[3][2][4][4];   // [plane][mt][nt][quad]
    #pragma unroll
    for (int p = 0; p < 3; ++p)
        #pragma unroll
        for (int mt = 0; mt < 2; ++mt)
            #pragma unroll
            for (int nt = 0; nt < 4; ++nt)
                #pragma unroll
                for (int q = 0; q < 4; ++q) acc[p][mt][nt][q] = 0.0f;

    // staging regs (fused fp32->bf16 hi/lo conversion — proven hidden)
    float Ar0[8], Ar1[8], Ai0[8], Ai1[8];
    float Br0[4], Br1[4], Bi0[4], Bi1[4];

    // precomputed STS byte offsets (tile-invariant)
    u32 offA[8], offB[4];
    #pragma unroll
    for (int it = 0; it < 8; ++it) {
        int idx = tid + it * THREADS;          // 0..2047
        offA[it] = sts_off_a(idx >> 4, idx & 15);
    }
    #pragma unroll
    for (int it = 0; it < 4; ++it) {
        int idx = tid + it * THREADS;          // 0..1023
        offB[it] = sts_off_b(idx & 63, idx >> 6);
    }

    auto load_regs = [&](int t) {
        const int k0 = t * TKt;
        if (k0 < Nn) {
            #pragma unroll
            for (int it = 0; it < 8; ++it) {
                int idx = tid + it * THREADS;
                int kp = idx & 15, n = idx >> 4;
                int g = 1023 + (row0 + n) - (k0 + 2 * kp);
                Ar0[it] = v_re[g]; Ar1[it] = v_re[g - 1];
                Ai0[it] = v_im[g]; Ai1[it] = v_im[g - 1];
            }
        } else {
            #pragma unroll
            for (int it = 0; it < 8; ++it) {
                int idx = tid + it * THREADS;
                int kp = idx & 15, n = idx >> 4;
                int g = (row0 + n) * Mm + (k0 - Nn + 2 * kp);
                Ar0[it] = W2_re[g]; Ar1[it] = W2_re[g + 1];
                Ai0[it] = W2_im[g]; Ai1[it] = W2_im[g + 1];
            }
        }
        const float* sr = (k0 < Nn) ? x_re : y_re;
        const float* si = (k0 < Nn) ? x_im : y_im;
        const int kb = (k0 < Nn) ? k0 : (k0 - Nn);
        #pragma unroll
        for (int it = 0; it < 4; ++it) {
            int idx = tid + it * THREADS;
            int cc = idx & 63, kp = idx >> 6;
            int g = (kb + 2 * kp) * Bb + col0 + cc;
            Br0[it] = sr[g]; Br1[it] = sr[g + Bb];
            Bi0[it] = si[g]; Bi1[it] = si[g + Bb];
        }
    };

    auto store_smem = [&](int bf) {
        char* base = smem + bf * BUFSZ;
        #pragma unroll
        for (int it = 0; it < 8; ++it) {
            const u32 o = offA[it];
            u32 h, l;
            hilo(Ar0[it], Ar1[it], h, l);
            *(u32*)(base + o) = h; *(u32*)(base + APL + o) = l;
            hilo(Ai0[it], Ai1[it], h, l);
            *(u32*)(base + 2 * APL + o) = h; *(u32*)(base + 3 * APL + o) = l;
            hilo(Ar0[it] + Ai0[it], Ar1[it] + Ai1[it], h, l);
            *(u32*)(base + 4 * APL + o) = h; *(u32*)(base + 5 * APL + o) = l;
        }
        char* Bb0 = base + 6 * APL;
        #pragma unroll
        for (int it = 0; it < 4; ++it) {
            const u32 o = offB[it];
            u32 h, l;
            hilo(Br0[it], Br1[it], h, l);
            *(u32*)(Bb0 + o) = h; *(u32*)(Bb0 + BPL + o) = l;
            hilo(Bi0[it], Bi1[it], h, l);
            *(u32*)(Bb0 + 2 * BPL + o) = h; *(u32*)(Bb0 + 3 * BPL + o) = l;
            hilo(Br0[it] + Bi0[it], Br1[it] + Bi1[it], h, l);
            *(u32*)(Bb0 + 4 * BPL + o) = h; *(u32*)(Bb0 + 5 * BPL + o) = l;
        }
    };

    load_regs(0);
    store_smem(0);
    __syncthreads();

    for (int t = 0; t < NTIL; ++t) {
        const int buf = t & 1;
        if (t + 1 < NTIL) load_regs(t + 1);

        const u32 base = smb + buf * BUFSZ;
        #pragma unroll
        for (int ks = 0; ks < 2; ++ks) {
            const u32 ko = (u32)(ks * 512) + lane16;
            #pragma unroll
            for (int p = 0; p < 3; ++p) {
                const u32 Ah = base + (2 * p) * APL;
                const u32 Al = Ah + APL;
                const u32 Bh = base + 6 * APL + (2 * p) * BPL;
                const u32 Bl = Bh + BPL;
                // one LDS.128 per fragment (a0..a3) / fragment-pair (b0,b1 x2)
                uint4 ah0 = lds128(Ah + (u32)((wr * 2) * 1024) + ko);
                uint4 ah1 = lds128(Ah + (u32)((wr * 2 + 1) * 1024) + ko);
                uint4 al0 = lds128(Al + (u32)((wr * 2) * 1024) + ko);
                uint4 al1 = lds128(Al + (u32)((wr * 2 + 1) * 1024) + ko);
                uint4 bh0 = lds128(Bh + (u32)((wc * 2) * 1024) + ko);
                uint4 bh1 = lds128(Bh + (u32)((wc * 2 + 1) * 1024) + ko);
                uint4 bl0 = lds128(Bl + (u32)((wc * 2) * 1024) + ko);
                uint4 bl1 = lds128(Bl + (u32)((wc * 2 + 1) * 1024) + ko);
                #pragma unroll
                for (int mt = 0; mt < 2; ++mt) {
                    const uint4& ah = mt ? ah1 : ah0;
                    const uint4& al = mt ? al1 : al0;
                    mma16816(acc[p][mt][0], ah, bh0.x, bh0.y);
                    mma16816(acc[p][mt][0], ah, bl0.x, bl0.y);
                    mma16816(acc[p][mt][0], al, bh0.x, bh0.y);
                    mma16816(acc[p][mt][1], ah, bh0.z, bh0.w);
                    mma16816(acc[p][mt][1], ah, bl0.z, bl0.w);
                    mma16816(acc[p][mt][1], al, bh0.z, bh0.w);
                    mma16816(acc[p][mt][2], ah, bh1.x, bh1.y);
                    mma16816(acc[p][mt][2], ah, bl1.x, bl1.y);
                    mma16816(acc[p][mt][2], al, bh1.x, bh1.y);
                    mma16816(acc[p][mt][3], ah, bh1.z, bh1.w);
                    mma16816(acc[p][mt][3], ah, bl1.z, bl1.w);
                    mma16816(acc[p][mt][3], al, bh1.z, bh1.w);
                }
            }
        }

        if (t + 1 < NTIL) store_smem(buf ^ 1);
        __syncthreads();
    }

    // ---- epilogue: re = P1-P2, im = P3-P1-P2, soft-threshold, store ----
    const int wm = wr * 32, wn = wc * 32;
    #pragma unroll
    for (int mt = 0; mt < 2; ++mt) {
        #pragma unroll
        for (int nt = 0; nt < 4; ++nt) {
            #pragma unroll
            for (int half = 0; half < 2; ++half) {
                const int q0 = half * 2;
                const int row = row0 + wm + mt * 16 + r4 + half * 8;
                const int col = col0 + wn + nt * 8 + c2;
                float p1a = acc[0][mt][nt][q0],     p1b = acc[0][mt][nt][q0 + 1];
                float p2a = acc[1][mt][nt][q0],     p2b = acc[1][mt][nt][q0 + 1];
                float p3a = acc[2][mt][nt][q0],     p3b = acc[2][mt][nt][q0 + 1];
                float rea = p1a - p2a,  reb = p1b - p2b;
                float ima = p3a - p1a - p2a, imb = p3b - p1b - p2b;
                float maga = sqrtf(rea * rea + ima * ima);
                float sca  = fmaxf(maga - BETA, 0.0f) / fmaxf(maga, EPSL);
                float magb = sqrtf(reb * reb + imb * imb);
                float scb  = fmaxf(magb - BETA, 0.0f) / fmaxf(magb, EPSL);
                rea *= sca; ima *= sca; reb *= scb; imb *= scb;
                const int e = row * Bb + col;
                if (omode == 0) {
                    __nv_bfloat162 pa = __floats2bfloat162_rn(rea, ima);
                    __nv_bfloat162 pb = __floats2bfloat162_rn(reb, imb);
                    u32 ua, ub; memcpy(&ua, &pa, 4); memcpy(&ub, &pb, 4);
                    *(uint2*)((u32*)out + e) = make_uint2(ua, ub);
                } else {
                    *(float2*)((float*)out + e) = make_float2(rea, reb);
                }
            }
        }
    }
}

extern "C" void kernel_launch(void* const* d_in, const int* in_sizes, int n_in,
                              void* d_out, int out_size) {
    // Crash-proof input dispatch: classify by element count (elements or bytes).
    int scale = 1;
    bool have2047 = false, have8188 = false;
    for (int i = 0; i < n_in && i < 8; ++i) {
        if (in_sizes[i] == 2 * Nn - 1) have2047 = true;
        if (in_sizes[i] == (2 * Nn - 1) * 4) have8188 = true;
    }
    if (!have2047 && have8188) scale = 4;

    const float* vp[2] = {0, 0};
    const float* xp[2] = {0, 0};
    const float* mp[4] = {0, 0, 0, 0};
    int nv = 0, nx = 0, nm = 0;
    for (int i = 0; i < n_in && i < 8; ++i) {
        const float* p = (const float*)d_in[i];
        long s = in_sizes[i];
        if (s == (long)(2 * Nn - 1) * scale)      { if (nv < 2) vp[nv++] = p; }
        else if (s == (long)Nn * Bb * scale)      { if (nx < 2) xp[nx++] = p; }
        else if (s == (long)Nn * Mm * scale)      { if (nm < 4) mp[nm++] = p; }
    }
    const float* v_re  = vp[0] ? vp[0] : (const float*)d_in[0];
    const float* v_im  = vp[1] ? vp[1] : (const float*)d_in[1];
    const float* W2_re = mp[0] ? mp[0] : (const float*)d_in[2];
    const float* W2_im = mp[1] ? mp[1] : (const float*)d_in[3];
    const float* x_re  = xp[0] ? xp[0] : (const float*)d_in[4];
    const float* x_im  = xp[1] ? xp[1] : (const float*)d_in[5];
    const float* y_re  = mp[2] ? mp[2] : (const float*)d_in[6];
    const float* y_im  = mp[3] ? mp[3] : (const float*)d_in[7];

    const int omode = (out_size >= 2 * Nn * Bb) ? 0 : 1;

    cudaFuncSetAttribute(toeplitz_hmma4_kernel,
                         cudaFuncAttributeMaxDynamicSharedMemorySize, SMTOT);
    dim3 grid(Bb / TNt, Nn / TMt);   // (16, 8) = 128 CTAs
    toeplitz_hmma4_kernel<<<grid, THREADS, SMTOT>>>(
        v_re, v_im, W2_re, W2_im, x_re, x_im, y_re, y_im,
        d_out, omode);
}

// round 11
// speedup vs baseline: 1.5364x; 1.2502x over previous
#include <cuda_runtime.h>
#include <cuda_bf16.h>
#include <cuda_fp16.h>
#include <cstdint>
#include <cstring>

#define Nn 1024
#define Mm 256
#define Bb 1024
#define Kk 1280
#define TMt 128           // CTA tile rows
#define TNt 64            // CTA tile cols
#define TKt 32            // K per staged tile
#define NTIL 40
#define BETA 0.01f
#define EPSL 1e-12f
#define THREADS 256

typedef uint32_t u32;

// Fragment-packed plane layout (per k-tile):
//  A plane: [m16 tile 0..7][kstep 0..1][lane 0..31][16B]  = 8192 B
//  B plane: [n8-pair 0..3][kstep 0..1][lane 0..31][16B]   = 4096 B
// A: 6 fp16 planes (rh,rl,ih,il,sh,sl). B: 3 fp16 planes (rh,ih,sh).
#define APL 8192
#define BPL 4096
#define BUFSZ (6 * APL + 3 * BPL)    // 61440
#define SMTOT (2 * BUFSZ)            // 122880 B

static __device__ __forceinline__ void hilo16(float a, float b, u32& h, u32& l) {
    __half2 t = __floats2half2_rn(a, b);
    memcpy(&h, &t, 4);
    float fa = __half2float(__low2half(t));
    float fb = __half2float(__high2half(t));
    __half2 t2 = __floats2half2_rn(a - fa, b - fb);
    memcpy(&l, &t2, 4);
}
static __device__ __forceinline__ u32 pk16(float a, float b) {
    __half2 t = __floats2half2_rn(a, b);
    u32 h; memcpy(&h, &t, 4); return h;
}
static __device__ __forceinline__ u32 smem_u32(const void* p) {
    u32 a;
    asm("{ .reg .u64 t; cvta.to.shared.u64 t, %1; cvt.u32.u64 %0, t; }" : "=r"(a) : "l"(p));
    return a;
}
static __device__ __forceinline__ uint4 lds128(u32 addr) {
    uint4 r;
    asm volatile("ld.shared.v4.b32 {%0,%1,%2,%3}, [%4];"
                 : "=r"(r.x), "=r"(r.y), "=r"(r.z), "=r"(r.w) : "r"(addr));
    return r;
}
static __device__ __forceinline__ void mma16816(float* c, const uint4& a, u32 b0, u32 b1) {
    asm volatile(
        "mma.sync.aligned.m16n8k16.row.col.f32.f16.f16.f32 "
        "{%0,%1,%2,%3}, {%4,%5,%6,%7}, {%8,%9}, {%0,%1,%2,%3};"
        : "+f"(c[0]), "+f"(c[1]), "+f"(c[2]), "+f"(c[3])
        : "r"(a.x), "r"(a.y), "r"(a.z), "r"(a.w), "r"(b0), "r"(b1));
}

// STS offset for A value (n, kp): fp16x2 of k=2kp,2kp+1 at row n.
static __device__ __forceinline__ u32 sts_off_a(int n, int kp) {
    int kpp = kp & 7;
    return (u32)((n >> 4) * 1024 + (kp >> 3) * 512 +
                 (((n & 7) * 4 + (kpp & 3)) * 16) +
                 (((kpp >= 4) ? 2 : 0) + ((n >> 3) & 1)) * 4);
}
// STS offset for B value (c, kp): fp16x2 of k=2kp,2kp+1 at col c.
static __device__ __forceinline__ u32 sts_off_b(int c, int kp) {
    int kpp = kp & 7;
    return (u32)((c >> 4) * 1024 + (kp >> 3) * 512 +
                 (((c & 7) * 4 + (kpp & 3)) * 16) +
                 ((((c >> 3) & 1) * 2) + ((kpp >= 4) ? 1 : 0)) * 4);
}

// z = softthresh(W1 @ x + W2 @ y); W1[n,k]=v[N-1+n-k].
// fp16 split-2 A (exact hi+lo), fp16 single B; Gauss 3-product; 6 MMA/complex.
__global__ __launch_bounds__(THREADS, 1)
void toeplitz_hmma5_kernel(
    const float* __restrict__ v_re,  const float* __restrict__ v_im,
    const float* __restrict__ W2_re, const float* __restrict__ W2_im,
    const float* __restrict__ x_re,  const float* __restrict__ x_im,
    const float* __restrict__ y_re,  const float* __restrict__ y_im,
    void* __restrict__ out, int omode)
{
    extern __shared__ char smem[];
    const u32 smb = smem_u32(smem);
    const int tid = threadIdx.x;
    const int wid = tid >> 5;
    const int lid = tid & 31;
    const int wr = wid >> 1, wc = wid & 1;    // 4x2 warp grid, warp tile 32x32
    const int r4 = lid >> 2;
    const int c2 = (lid & 3) * 2;
    const int row0 = blockIdx.y * TMt;
    const int col0 = blockIdx.x * TNt;
    const u32 lane16 = (u32)(lid * 16);

    float acc[3][2][4][4];   // [plane][mt][nt][quad]
    #pragma unroll
    for (int p = 0; p < 3; ++p)
        #pragma unroll
        for (int mt = 0; mt < 2; ++mt)
            #pragma unroll
            for (int nt = 0; nt < 4; ++nt)
                #pragma unroll
                for (int q = 0; q < 4; ++q) acc[p][mt][nt][q] = 0.0f;

    // staging regs (fused fp32->fp16 hi/lo conversion — proven hidden)
    float Ar0[8], Ar1[8], Ai0[8], Ai1[8];
    float Br0[4], Br1[4], Bi0[4], Bi1[4];

    // precomputed STS byte offsets (tile-invariant)
    u32 offA[8], offB[4];
    #pragma unroll
    for (int it = 0; it < 8; ++it) {
        int idx = tid + it * THREADS;          // 0..2047
        offA[it] = sts_off_a(idx >> 4, idx & 15);
    }
    #pragma unroll
    for (int it = 0; it < 4; ++it) {
        int idx = tid + it * THREADS;          // 0..1023
        offB[it] = sts_off_b(idx & 63, idx >> 6);
    }

    auto load_regs = [&](int t) {
        const int k0 = t * TKt;
        if (k0 < Nn) {
            #pragma unroll
            for (int it = 0; it < 8; ++it) {
                int idx = tid + it * THREADS;
                int kp = idx & 15, n = idx >> 4;
                int g = 1023 + (row0 + n) - (k0 + 2 * kp);
                Ar0[it] = v_re[g]; Ar1[it] = v_re[g - 1];
                Ai0[it] = v_im[g]; Ai1[it] = v_im[g - 1];
            }
        } else {
            #pragma unroll
            for (int it = 0; it < 8; ++it) {
                int idx = tid + it * THREADS;
                int kp = idx & 15, n = idx >> 4;
                int g = (row0 + n) * Mm + (k0 - Nn + 2 * kp);
                Ar0[it] = W2_re[g]; Ar1[it] = W2_re[g + 1];
                Ai0[it] = W2_im[g]; Ai1[it] = W2_im[g + 1];
            }
        }
        const float* sr = (k0 < Nn) ? x_re : y_re;
        const float* si = (k0 < Nn) ? x_im : y_im;
        const int kb = (k0 < Nn) ? k0 : (k0 - Nn);
        #pragma unroll
        for (int it = 0; it < 4; ++it) {
            int idx = tid + it * THREADS;
            int cc = idx & 63, kp = idx >> 6;
            int g = (kb + 2 * kp) * Bb + col0 + cc;
            Br0[it] = sr[g]; Br1[it] = sr[g + Bb];
            Bi0[it] = si[g]; Bi1[it] = si[g + Bb];
        }
    };

    auto store_smem = [&](int bf) {
        char* base = smem + bf * BUFSZ;
        #pragma unroll
        for (int it = 0; it < 8; ++it) {
            const u32 o = offA[it];
            u32 h, l;
            hilo16(Ar0[it], Ar1[it], h, l);
            *(u32*)(base + o) = h; *(u32*)(base + APL + o) = l;
            hilo16(Ai0[it], Ai1[it], h, l);
            *(u32*)(base + 2 * APL + o) = h; *(u32*)(base + 3 * APL + o) = l;
            hilo16(Ar0[it] + Ai0[it], Ar1[it] + Ai1[it], h, l);
            *(u32*)(base + 4 * APL + o) = h; *(u32*)(base + 5 * APL + o) = l;
        }
        char* Bb0 = base + 6 * APL;
        #pragma unroll
        for (int it = 0; it < 4; ++it) {
            const u32 o = offB[it];
            *(u32*)(Bb0 + o)           = pk16(Br0[it], Br1[it]);
            *(u32*)(Bb0 + BPL + o)     = pk16(Bi0[it], Bi1[it]);
            *(u32*)(Bb0 + 2 * BPL + o) = pk16(Br0[it] + Bi0[it], Br1[it] + Bi1[it]);
        }
    };

    load_regs(0);
    store_smem(0);
    __syncthreads();

    for (int t = 0; t < NTIL; ++t) {
        const int buf = t & 1;
        if (t + 1 < NTIL) load_regs(t + 1);

        const u32 base = smb + buf * BUFSZ;
        #pragma unroll
        for (int ks = 0; ks < 2; ++ks) {
            const u32 ko = (u32)(ks * 512) + lane16;
            #pragma unroll
            for (int p = 0; p < 3; ++p) {
                const u32 Ah = base + (2 * p) * APL;
                const u32 Al = Ah + APL;
                const u32 Bh = base + 6 * APL + p * BPL;
                uint4 ah0 = lds128(Ah + (u32)((wr * 2) * 1024) + ko);
                uint4 ah1 = lds128(Ah + (u32)((wr * 2 + 1) * 1024) + ko);
                uint4 al0 = lds128(Al + (u32)((wr * 2) * 1024) + ko);
                uint4 al1 = lds128(Al + (u32)((wr * 2 + 1) * 1024) + ko);
                uint4 bh0 = lds128(Bh + (u32)((wc * 2) * 1024) + ko);
                uint4 bh1 = lds128(Bh + (u32)((wc * 2 + 1) * 1024) + ko);
                #pragma unroll
                for (int mt = 0; mt < 2; ++mt) {
                    const uint4& ah = mt ? ah1 : ah0;
                    const uint4& al = mt ? al1 : al0;
                    mma16816(acc[p][mt][0], ah, bh0.x, bh0.y);
                    mma16816(acc[p][mt][0], al, bh0.x, bh0.y);
                    mma16816(acc[p][mt][1], ah, bh0.z, bh0.w);
                    mma16816(acc[p][mt][1], al, bh0.z, bh0.w);
                    mma16816(acc[p][mt][2], ah, bh1.x, bh1.y);
                    mma16816(acc[p][mt][2], al, bh1.x, bh1.y);
                    mma16816(acc[p][mt][3], ah, bh1.z, bh1.w);
                    mma16816(acc[p][mt][3], al, bh1.z, bh1.w);
                }
            }
        }

        if (t + 1 < NTIL) store_smem(buf ^ 1);
        __syncthreads();
    }

    // ---- epilogue: re = P1-P2, im = P3-P1-P2, soft-threshold, store ----
    const int wm = wr * 32, wn = wc * 32;
    #pragma unroll
    for (int mt = 0; mt < 2; ++mt) {
        #pragma unroll
        for (int nt = 0; nt < 4; ++nt) {
            #pragma unroll
            for (int half = 0; half < 2; ++half) {
                const int q0 = half * 2;
                const int row = row0 + wm + mt * 16 + r4 + half * 8;
                const int col = col0 + wn + nt * 8 + c2;
                float p1a = acc[0][mt][nt][q0],     p1b = acc[0][mt][nt][q0 + 1];
                float p2a = acc[1][mt][nt][q0],     p2b = acc[1][mt][nt][q0 + 1];
                float p3a = acc[2][mt][nt][q0],     p3b = acc[2][mt][nt][q0 + 1];
                float rea = p1a - p2a,  reb = p1b - p2b;
                float ima = p3a - p1a - p2a, imb = p3b - p1b - p2b;
                float maga = sqrtf(rea * rea + ima * ima);
                float sca  = fmaxf(maga - BETA, 0.0f) / fmaxf(maga, EPSL);
                float magb = sqrtf(reb * reb + imb * imb);
                float scb  = fmaxf(magb - BETA, 0.0f) / fmaxf(magb, EPSL);
                rea *= sca; ima *= sca; reb *= scb; imb *= scb;
                const int e = row * Bb + col;
                if (omode == 0) {
                    __nv_bfloat162 pa = __floats2bfloat162_rn(rea, ima);
                    __nv_bfloat162 pb = __floats2bfloat162_rn(reb, imb);
                    u32 ua, ub; memcpy(&ua, &pa, 4); memcpy(&ub, &pb, 4);
                    *(uint2*)((u32*)out + e) = make_uint2(ua, ub);
                } else {
                    *(float2*)((float*)out + e) = make_float2(rea, reb);
                }
            }
        }
    }
}

extern "C" void kernel_launch(void* const* d_in, const int* in_sizes, int n_in,
                              void* d_out, int out_size) {
    // Crash-proof input dispatch: classify by element count (elements or bytes).
    int scale = 1;
    bool have2047 = false, have8188 = false;
    for (int i = 0; i < n_in && i < 8; ++i) {
        if (in_sizes[i] == 2 * Nn - 1) have2047 = true;
        if (in_sizes[i] == (2 * Nn - 1) * 4) have8188 = true;
    }
    if (!have2047 && have8188) scale = 4;

    const float* vp[2] = {0, 0};
    const float* xp[2] = {0, 0};
    const float* mp[4] = {0, 0, 0, 0};
    int nv = 0, nx = 0, nm = 0;
    for (int i = 0; i < n_in && i < 8; ++i) {
        const float* p = (const float*)d_in[i];
        long s = in_sizes[i];
        if (s == (long)(2 * Nn - 1) * scale)      { if (nv < 2) vp[nv++] = p; }
        else if (s == (long)Nn * Bb * scale)      { if (nx < 2) xp[nx++] = p; }
        else if (s == (long)Nn * Mm * scale)      { if (nm < 4) mp[nm++] = p; }
    }
    const float* v_re  = vp[0] ? vp[0] : (const float*)d_in[0];
    const float* v_im  = vp[1] ? vp[1] : (const float*)d_in[1];
    const float* W2_re = mp[0] ? mp[0] : (const float*)d_in[2];
    const float* W2_im = mp[1] ? mp[1] : (const float*)d_in[3];
    const float* x_re  = xp[0] ? xp[0] : (const float*)d_in[4];
    const float* x_im  = xp[1] ? xp[1] : (const float*)d_in[5];
    const float* y_re  = mp[2] ? mp[2] : (const float*)d_in[6];
    const float* y_im  = mp[3] ? mp[3] : (const float*)d_in[7];

    const int omode = (out_size >= 2 * Nn * Bb) ? 0 : 1;

    cudaFuncSetAttribute(toeplitz_hmma5_kernel,
                         cudaFuncAttributeMaxDynamicSharedMemorySize, SMTOT);
    dim3 grid(Bb / TNt, Nn / TMt);   // (16, 8) = 128 CTAs
    toeplitz_hmma5_kernel<<<grid, THREADS, SMTOT>>>(
        v_re, v_im, W2_re, W2_im, x_re, x_im, y_re, y_im,
        d_out, omode);
}